// round 1
// baseline (speedup 1.0000x reference)
#include <cuda_runtime.h>
#include <math.h>

#define EPSF 1e-5f

// ---------------- scratch (static device allocations; no cudaMalloc) ----------------
__device__ float g_xq[4194304];    // quantized x        [4096,1024]
__device__ float g_cq[4194304];    // quantized context  [4096,1024]
__device__ float g_wqd[4194304];   // quantized weights  4 x [1024,1024] (q,k,v,o)
__device__ float g_q[4194304];     // Q  [4096, 16*64]
__device__ float g_k[4194304];     // K
__device__ float g_v[4194304];     // V
__device__ float g_attn[4194304];  // attention output [4096,1024]
__device__ float g_aq[4194304];    // quantized attention output
__device__ double g_wpart[256];    // 4 matrices x 64 partial sums
__device__ float g_wcm[4];         // clipped mean |w|
__device__ float g_wscale[4];      // 1 / clipped mean

// ---------------- weight |w| sum (double accumulation, deterministic) ----------------
__global__ __launch_bounds__(256) void wsum_kernel(const float* __restrict__ w0,
                                                   const float* __restrict__ w1,
                                                   const float* __restrict__ w2,
                                                   const float* __restrict__ w3)
{
    const float* w = (blockIdx.y == 0) ? w0 : (blockIdx.y == 1) ? w1 : (blockIdx.y == 2) ? w2 : w3;
    int base = blockIdx.x * 16384;
    int t = threadIdx.x;
    double s = 0.0;
    #pragma unroll
    for (int i = 0; i < 16; i++) {
        float4 v = *(const float4*)(w + base + i * 1024 + t * 4);
        s += (double)fabsf(v.x) + (double)fabsf(v.y) + (double)fabsf(v.z) + (double)fabsf(v.w);
    }
    #pragma unroll
    for (int o = 16; o > 0; o >>= 1) s += __shfl_down_sync(0xffffffffu, s, o);
    __shared__ double ws[8];
    if ((t & 31) == 0) ws[t >> 5] = s;
    __syncthreads();
    if (t == 0) {
        double tot = 0.0;
        #pragma unroll
        for (int i = 0; i < 8; i++) tot += ws[i];
        g_wpart[blockIdx.y * 64 + blockIdx.x] = tot;
    }
}

__global__ void wscale_kernel()
{
    int m = blockIdx.x;
    int t = threadIdx.x; // 64 threads
    double s = g_wpart[m * 64 + t];
    #pragma unroll
    for (int o = 16; o > 0; o >>= 1) s += __shfl_down_sync(0xffffffffu, s, o);
    __shared__ double a[2];
    if ((t & 31) == 0) a[t >> 5] = s;
    __syncthreads();
    if (t == 0) {
        float mean = (float)((a[0] + a[1]) / 1048576.0);
        float cm = fmaxf(mean, EPSF);
        g_wcm[m] = cm;
        g_wscale[m] = 1.0f / cm;
    }
}

__global__ __launch_bounds__(256) void wquant_kernel(const float* __restrict__ w0,
                                                     const float* __restrict__ w1,
                                                     const float* __restrict__ w2,
                                                     const float* __restrict__ w3)
{
    int m = blockIdx.y;
    const float* w = (m == 0) ? w0 : (m == 1) ? w1 : (m == 2) ? w2 : w3;
    float s = g_wscale[m];
    float cm = g_wcm[m];
    int idx = (blockIdx.x * 256 + threadIdx.x) * 4;
    float4 v = *(const float4*)(w + idx);
    float4 o;
    o.x = fminf(fmaxf(rintf(v.x * s), -1.f), 1.f) * cm;
    o.y = fminf(fmaxf(rintf(v.y * s), -1.f), 1.f) * cm;
    o.z = fminf(fmaxf(rintf(v.z * s), -1.f), 1.f) * cm;
    o.w = fminf(fmaxf(rintf(v.w * s), -1.f), 1.f) * cm;
    *(float4*)(g_wqd + m * 1048576 + idx) = o;
}

// ---------------- per-token int8 absmax quant (exact match with reference) ----------------
__global__ __launch_bounds__(256) void act_quant_kernel(const float* __restrict__ in,
                                                        float* __restrict__ out)
{
    int row = blockIdx.x;
    int t = threadIdx.x;
    const float4* ri = (const float4*)(in + (size_t)row * 1024);
    float4 v = ri[t];
    float am = fmaxf(fmaxf(fabsf(v.x), fabsf(v.y)), fmaxf(fabsf(v.z), fabsf(v.w)));
    #pragma unroll
    for (int o = 16; o > 0; o >>= 1) am = fmaxf(am, __shfl_xor_sync(0xffffffffu, am, o));
    __shared__ float wm[8];
    if ((t & 31) == 0) wm[t >> 5] = am;
    __syncthreads();
    am = wm[0];
    #pragma unroll
    for (int i = 1; i < 8; i++) am = fmaxf(am, wm[i]);
    float amax = fmaxf(am, EPSF);
    float scale = 127.0f / amax;
    float inv = 1.0f / scale;
    float4 o4;
    float r;
    r = fminf(fmaxf(rintf(v.x * scale), -128.f), 127.f); o4.x = r * inv;
    r = fminf(fmaxf(rintf(v.y * scale), -128.f), 127.f); o4.y = r * inv;
    r = fminf(fmaxf(rintf(v.z * scale), -128.f), 127.f); o4.z = r * inv;
    r = fminf(fmaxf(rintf(v.w * scale), -128.f), 127.f); o4.w = r * inv;
    ((float4*)(out + (size_t)row * 1024))[t] = o4;
}

// ---------------- SGEMM: C[M,N] = A[M,K] * B[N,K]^T (all row-major) ----------------
// 128x128 block tile, BK=16, 256 threads, 8x8 per thread.
__global__ __launch_bounds__(256) void sgemm_nt(const float* __restrict__ A,
                                                const float* __restrict__ B,
                                                float* __restrict__ C,
                                                int M, int N, int K)
{
    __shared__ float As[16][132];
    __shared__ float Bs[16][132];
    int tid = threadIdx.x;
    int tx = tid & 15, ty = tid >> 4;
    const float* Ag = A + (size_t)(blockIdx.y * 128) * K;
    const float* Bg = B + (size_t)(blockIdx.x * 128) * K;
    int lr = tid >> 2;          // 0..63
    int lc = (tid & 3) * 4;     // 0,4,8,12

    float acc[8][8];
    #pragma unroll
    for (int i = 0; i < 8; i++)
        #pragma unroll
        for (int j = 0; j < 8; j++) acc[i][j] = 0.f;

    for (int k0 = 0; k0 < K; k0 += 16) {
        float4 a0 = *(const float4*)(Ag + (size_t)lr * K + k0 + lc);
        float4 a1 = *(const float4*)(Ag + (size_t)(lr + 64) * K + k0 + lc);
        float4 b0 = *(const float4*)(Bg + (size_t)lr * K + k0 + lc);
        float4 b1 = *(const float4*)(Bg + (size_t)(lr + 64) * K + k0 + lc);
        __syncthreads();
        As[lc + 0][lr] = a0.x; As[lc + 1][lr] = a0.y; As[lc + 2][lr] = a0.z; As[lc + 3][lr] = a0.w;
        As[lc + 0][lr + 64] = a1.x; As[lc + 1][lr + 64] = a1.y; As[lc + 2][lr + 64] = a1.z; As[lc + 3][lr + 64] = a1.w;
        Bs[lc + 0][lr] = b0.x; Bs[lc + 1][lr] = b0.y; Bs[lc + 2][lr] = b0.z; Bs[lc + 3][lr] = b0.w;
        Bs[lc + 0][lr + 64] = b1.x; Bs[lc + 1][lr + 64] = b1.y; Bs[lc + 2][lr + 64] = b1.z; Bs[lc + 3][lr + 64] = b1.w;
        __syncthreads();
        #pragma unroll
        for (int kk = 0; kk < 16; kk++) {
            float ra[8], rb[8];
            *(float4*)&ra[0] = *(const float4*)&As[kk][ty * 8];
            *(float4*)&ra[4] = *(const float4*)&As[kk][ty * 8 + 4];
            *(float4*)&rb[0] = *(const float4*)&Bs[kk][tx * 8];
            *(float4*)&rb[4] = *(const float4*)&Bs[kk][tx * 8 + 4];
            #pragma unroll
            for (int i = 0; i < 8; i++)
                #pragma unroll
                for (int j = 0; j < 8; j++)
                    acc[i][j] += ra[i] * rb[j];
        }
    }
    float* Cg = C + (size_t)(blockIdx.y * 128 + ty * 8) * N + blockIdx.x * 128 + tx * 8;
    #pragma unroll
    for (int i = 0; i < 8; i++) {
        *(float4*)(Cg + (size_t)i * N)     = make_float4(acc[i][0], acc[i][1], acc[i][2], acc[i][3]);
        *(float4*)(Cg + (size_t)i * N + 4) = make_float4(acc[i][4], acc[i][5], acc[i][6], acc[i][7]);
    }
}

// ---------------- flash attention (fp32), 64 q-rows x 32-key tiles, d=64 ----------------
// grid (32 qblocks, 16 heads, 2 batch), 256 threads (16x16).
__global__ __launch_bounds__(256) void attn_kernel(const float* __restrict__ Q,
                                                   const float* __restrict__ K,
                                                   const float* __restrict__ V,
                                                   float* __restrict__ O)
{
    __shared__ float Qs[64 * 64];   // Q^T: Qs[d*64 + i], pre-scaled by 1/8
    __shared__ float Ks[64 * 34];   // K^T: Ks[d*34 + j]; reused as P^T: Ps[j*68 + i] (2176 floats)
    __shared__ float Vs[32 * 64];   // Vs[j*64 + d]
    int b = blockIdx.z, h = blockIdx.y, qb = blockIdx.x;
    int tid = threadIdx.x;
    int tx = tid & 15, ty = tid >> 4;
    const float* Qg = Q + ((size_t)(b * 2048 + qb * 64)) * 1024 + h * 64;
    const float* Kg = K + ((size_t)b * 2048) * 1024 + h * 64;
    const float* Vg = V + ((size_t)b * 2048) * 1024 + h * 64;

    // load Q tile transposed, fold in softmax scale (1/sqrt(64) = 0.125, exact)
    #pragma unroll
    for (int it = 0; it < 4; it++) {
        int i = (tid >> 4) + it * 16;
        int d = (tid & 15) * 4;
        float4 q4 = *(const float4*)(Qg + (size_t)i * 1024 + d);
        Qs[(d + 0) * 64 + i] = q4.x * 0.125f;
        Qs[(d + 1) * 64 + i] = q4.y * 0.125f;
        Qs[(d + 2) * 64 + i] = q4.z * 0.125f;
        Qs[(d + 3) * 64 + i] = q4.w * 0.125f;
    }

    float m_r[4], l_r[4], oa[4][4];
    #pragma unroll
    for (int r = 0; r < 4; r++) {
        m_r[r] = -1e30f; l_r[r] = 0.f;
        #pragma unroll
        for (int c = 0; c < 4; c++) oa[r][c] = 0.f;
    }

    for (int j0 = 0; j0 < 2048; j0 += 32) {
        __syncthreads();  // previous tile's Ps/Vs readers done
        #pragma unroll
        for (int it = 0; it < 2; it++) {
            int j = (tid >> 4) + it * 16;
            int d = (tid & 15) * 4;
            float4 k4 = *(const float4*)(Kg + (size_t)(j0 + j) * 1024 + d);
            Ks[(d + 0) * 34 + j] = k4.x;
            Ks[(d + 1) * 34 + j] = k4.y;
            Ks[(d + 2) * 34 + j] = k4.z;
            Ks[(d + 3) * 34 + j] = k4.w;
            float4 v4 = *(const float4*)(Vg + (size_t)(j0 + j) * 1024 + d);
            *(float4*)&Vs[j * 64 + d] = v4;
        }
        __syncthreads();

        // S tile: rows i = ty*4+r, cols j = tx*2+c
        float s[4][2];
        #pragma unroll
        for (int r = 0; r < 4; r++) { s[r][0] = 0.f; s[r][1] = 0.f; }
        #pragma unroll
        for (int d = 0; d < 64; d++) {
            float4 qa = *(const float4*)&Qs[d * 64 + ty * 4];
            float2 kb = *(const float2*)&Ks[d * 34 + tx * 2];
            s[0][0] += qa.x * kb.x; s[0][1] += qa.x * kb.y;
            s[1][0] += qa.y * kb.x; s[1][1] += qa.y * kb.y;
            s[2][0] += qa.z * kb.x; s[2][1] += qa.z * kb.y;
            s[3][0] += qa.w * kb.x; s[3][1] += qa.w * kb.y;
        }

        // online softmax (row group = 16 lanes sharing ty; xor 1,2,4,8 stays in-group)
        #pragma unroll
        for (int r = 0; r < 4; r++) {
            float rm = fmaxf(s[r][0], s[r][1]);
            rm = fmaxf(rm, __shfl_xor_sync(0xffffffffu, rm, 1));
            rm = fmaxf(rm, __shfl_xor_sync(0xffffffffu, rm, 2));
            rm = fmaxf(rm, __shfl_xor_sync(0xffffffffu, rm, 4));
            rm = fmaxf(rm, __shfl_xor_sync(0xffffffffu, rm, 8));
            float mn = fmaxf(m_r[r], rm);
            float corr = __expf(m_r[r] - mn);
            m_r[r] = mn;
            float p0 = __expf(s[r][0] - mn);
            float p1 = __expf(s[r][1] - mn);
            s[r][0] = p0; s[r][1] = p1;
            float ps = p0 + p1;
            ps += __shfl_xor_sync(0xffffffffu, ps, 1);
            ps += __shfl_xor_sync(0xffffffffu, ps, 2);
            ps += __shfl_xor_sync(0xffffffffu, ps, 4);
            ps += __shfl_xor_sync(0xffffffffu, ps, 8);
            l_r[r] = l_r[r] * corr + ps;
            oa[r][0] *= corr; oa[r][1] *= corr; oa[r][2] *= corr; oa[r][3] *= corr;
        }
        __syncthreads();  // done reading Ks as K^T

        // write P^T into the K buffer: Ps[j*68 + i]
        float* Ps = Ks;
        #pragma unroll
        for (int c = 0; c < 2; c++)
            #pragma unroll
            for (int r = 0; r < 4; r++)
                Ps[(tx * 2 + c) * 68 + ty * 4 + r] = s[r][c];
        __syncthreads();

        // O += P @ V  (O rows i = ty*4+r, cols d = tx*4+c)
        #pragma unroll
        for (int j = 0; j < 32; j++) {
            float4 pa = *(const float4*)&Ps[j * 68 + ty * 4];
            float4 vb = *(const float4*)&Vs[j * 64 + tx * 4];
            oa[0][0] += pa.x * vb.x; oa[0][1] += pa.x * vb.y; oa[0][2] += pa.x * vb.z; oa[0][3] += pa.x * vb.w;
            oa[1][0] += pa.y * vb.x; oa[1][1] += pa.y * vb.y; oa[1][2] += pa.y * vb.z; oa[1][3] += pa.y * vb.w;
            oa[2][0] += pa.z * vb.x; oa[2][1] += pa.z * vb.y; oa[2][2] += pa.z * vb.z; oa[2][3] += pa.z * vb.w;
            oa[3][0] += pa.w * vb.x; oa[3][1] += pa.w * vb.y; oa[3][2] += pa.w * vb.z; oa[3][3] += pa.w * vb.w;
        }
    }

    float* Og = O + ((size_t)(b * 2048 + qb * 64)) * 1024 + h * 64;
    #pragma unroll
    for (int r = 0; r < 4; r++) {
        float invl = 1.0f / l_r[r];
        int i = ty * 4 + r;
        float4 o4 = make_float4(oa[r][0] * invl, oa[r][1] * invl, oa[r][2] * invl, oa[r][3] * invl);
        *(float4*)(Og + (size_t)i * 1024 + tx * 4) = o4;
    }
}

// ---------------- launch ----------------
extern "C" void kernel_launch(void* const* d_in, const int* in_sizes, int n_in,
                              void* d_out, int out_size)
{
    (void)in_sizes; (void)n_in; (void)out_size;
    const float* x   = (const float*)d_in[0];
    const float* ctx = (const float*)d_in[1];
    const float* wq  = (const float*)d_in[2];
    const float* wk  = (const float*)d_in[3];
    const float* wv  = (const float*)d_in[4];
    const float* wo  = (const float*)d_in[5];
    float* out = (float*)d_out;

    float *xq, *cq, *wqd, *q, *k, *v, *attn, *aq;
    cudaGetSymbolAddress((void**)&xq,   g_xq);
    cudaGetSymbolAddress((void**)&cq,   g_cq);
    cudaGetSymbolAddress((void**)&wqd,  g_wqd);
    cudaGetSymbolAddress((void**)&q,    g_q);
    cudaGetSymbolAddress((void**)&k,    g_k);
    cudaGetSymbolAddress((void**)&v,    g_v);
    cudaGetSymbolAddress((void**)&attn, g_attn);
    cudaGetSymbolAddress((void**)&aq,   g_aq);

    // weight quantization
    wsum_kernel<<<dim3(64, 4), 256>>>(wq, wk, wv, wo);
    wscale_kernel<<<4, 64>>>();
    wquant_kernel<<<dim3(1024, 4), 256>>>(wq, wk, wv, wo);

    // activation quantization
    act_quant_kernel<<<4096, 256>>>(x, xq);
    act_quant_kernel<<<4096, 256>>>(ctx, cq);

    // projections: [4096,1024] x [1024,1024]^T
    sgemm_nt<<<dim3(8, 32), 256>>>(xq, wqd,           q, 4096, 1024, 1024);
    sgemm_nt<<<dim3(8, 32), 256>>>(cq, wqd + 1048576, k, 4096, 1024, 1024);
    sgemm_nt<<<dim3(8, 32), 256>>>(cq, wqd + 2097152, v, 4096, 1024, 1024);

    // attention
    attn_kernel<<<dim3(32, 16, 2), 256>>>(q, k, v, attn);

    // output projection
    act_quant_kernel<<<4096, 256>>>(attn, aq);
    sgemm_nt<<<dim3(8, 32), 256>>>(aq, wqd + 3145728, out, 4096, 1024, 1024);
}

// round 4
// speedup vs baseline: 3.7911x; 3.7911x over previous
#include <cuda_runtime.h>
#include <cuda_fp16.h>
#include <math.h>
#include <stdint.h>

#define EPSF 1e-5f

// ---------------- scratch ----------------
__device__ int8_t g_xq[4194304];     // quantized x int8 [4096,1024]
__device__ int8_t g_cq[4194304];     // quantized context int8
__device__ int8_t g_aq[4194304];     // quantized attn-out int8
__device__ int8_t g_wt[4][1048576];  // ternary weights int8 (q,k,v,o)
__device__ float  g_xscale[4096];
__device__ float  g_cscale[4096];
__device__ float  g_ascale[4096];
__device__ __half g_qh[4194304];     // Q hi fp16 (pre-scaled by 0.125)
__device__ __half g_ql[4194304];     // Q lo fp16 (residual)
__device__ __half g_kh[4194304];     // K hi
__device__ __half g_kl[4194304];     // K lo
__device__ __half g_vh[4194304];     // V hi
__device__ __half g_vl[4194304];     // V lo
__device__ float  g_attn[4194304];   // attention output fp32
__device__ double g_wpart[256];
__device__ float  g_wcm[4];
__device__ float  g_wscale[4];

// ---------------- weight |w| sum (double accumulation, deterministic) ----------------
__global__ __launch_bounds__(256) void wsum_kernel(const float* __restrict__ w0,
                                                   const float* __restrict__ w1,
                                                   const float* __restrict__ w2,
                                                   const float* __restrict__ w3)
{
    const float* w = (blockIdx.y == 0) ? w0 : (blockIdx.y == 1) ? w1 : (blockIdx.y == 2) ? w2 : w3;
    int base = blockIdx.x * 16384;
    int t = threadIdx.x;
    double s = 0.0;
    #pragma unroll
    for (int i = 0; i < 16; i++) {
        float4 v = *(const float4*)(w + base + i * 1024 + t * 4);
        s += (double)fabsf(v.x) + (double)fabsf(v.y) + (double)fabsf(v.z) + (double)fabsf(v.w);
    }
    #pragma unroll
    for (int o = 16; o > 0; o >>= 1) s += __shfl_down_sync(0xffffffffu, s, o);
    __shared__ double ws[8];
    if ((t & 31) == 0) ws[t >> 5] = s;
    __syncthreads();
    if (t == 0) {
        double tot = 0.0;
        #pragma unroll
        for (int i = 0; i < 8; i++) tot += ws[i];
        g_wpart[blockIdx.y * 64 + blockIdx.x] = tot;
    }
}

__global__ void wscale_kernel()
{
    int m = blockIdx.x;
    int t = threadIdx.x; // 64 threads
    double s = g_wpart[m * 64 + t];
    #pragma unroll
    for (int o = 16; o > 0; o >>= 1) s += __shfl_down_sync(0xffffffffu, s, o);
    __shared__ double a[2];
    if ((t & 31) == 0) a[t >> 5] = s;
    __syncthreads();
    if (t == 0) {
        float mean = (float)((a[0] + a[1]) / 1048576.0);
        float cm = fmaxf(mean, EPSF);
        g_wcm[m] = cm;
        g_wscale[m] = 1.0f / cm;
    }
}

__global__ __launch_bounds__(256) void wquant_kernel(const float* __restrict__ w0,
                                                     const float* __restrict__ w1,
                                                     const float* __restrict__ w2,
                                                     const float* __restrict__ w3)
{
    int m = blockIdx.y;
    const float* w = (m == 0) ? w0 : (m == 1) ? w1 : (m == 2) ? w2 : w3;
    float s = g_wscale[m];
    int idx = (blockIdx.x * 256 + threadIdx.x) * 4;
    float4 v = *(const float4*)(w + idx);
    char4 o;
    o.x = (char)fminf(fmaxf(rintf(v.x * s), -1.f), 1.f);
    o.y = (char)fminf(fmaxf(rintf(v.y * s), -1.f), 1.f);
    o.z = (char)fminf(fmaxf(rintf(v.z * s), -1.f), 1.f);
    o.w = (char)fminf(fmaxf(rintf(v.w * s), -1.f), 1.f);
    *(char4*)(g_wt[m] + idx) = o;
}

// ---------------- per-token int8 absmax quant ----------------
__global__ __launch_bounds__(256) void act_quant_i8(const float* __restrict__ in,
                                                    int8_t* __restrict__ out,
                                                    float* __restrict__ rowscale)
{
    int row = blockIdx.x;
    int t = threadIdx.x;
    const float4* ri = (const float4*)(in + (size_t)row * 1024);
    float4 v = ri[t];
    float am = fmaxf(fmaxf(fabsf(v.x), fabsf(v.y)), fmaxf(fabsf(v.z), fabsf(v.w)));
    #pragma unroll
    for (int o = 16; o > 0; o >>= 1) am = fmaxf(am, __shfl_xor_sync(0xffffffffu, am, o));
    __shared__ float wm[8];
    if ((t & 31) == 0) wm[t >> 5] = am;
    __syncthreads();
    am = wm[0];
    #pragma unroll
    for (int i = 1; i < 8; i++) am = fmaxf(am, wm[i]);
    float amax = fmaxf(am, EPSF);
    float scale = 127.0f / amax;
    char4 o4;
    o4.x = (char)fminf(fmaxf(rintf(v.x * scale), -128.f), 127.f);
    o4.y = (char)fminf(fmaxf(rintf(v.y * scale), -128.f), 127.f);
    o4.z = (char)fminf(fmaxf(rintf(v.z * scale), -128.f), 127.f);
    o4.w = (char)fminf(fmaxf(rintf(v.w * scale), -128.f), 127.f);
    *(char4*)(out + (size_t)row * 1024 + t * 4) = o4;
    if (t == 0) rowscale[row] = amax * (1.0f / 127.0f);
}

// ---------------- int8 tensor-core GEMM ----------------
__device__ __forceinline__ void mma_s8(int* c, const uint32_t* a, const uint32_t* b)
{
    asm volatile(
        "mma.sync.aligned.m16n8k32.row.col.s32.s8.s8.s32 "
        "{%0,%1,%2,%3}, {%4,%5,%6,%7}, {%8,%9}, {%0,%1,%2,%3};"
        : "+r"(c[0]), "+r"(c[1]), "+r"(c[2]), "+r"(c[3])
        : "r"(a[0]), "r"(a[1]), "r"(a[2]), "r"(a[3]), "r"(b[0]), "r"(b[1]));
}

// OUT_MODE: 0 = float, 2 = half hi/lo split
template <int OUT_MODE>
__global__ __launch_bounds__(256) void gemm_s8_nt(const int8_t* __restrict__ A,
                                                  const int8_t* __restrict__ Bm,
                                                  const float* __restrict__ ascale,
                                                  int midx,
                                                  void* __restrict__ Cout,
                                                  void* __restrict__ Cout2,
                                                  float mult)
{
    __shared__ int8_t sm[2][20480];  // [buf][A:128*80 | B:128*80]
    int tid = threadIdx.x;
    int w = tid >> 5, lane = tid & 31;
    int grp = lane >> 2, q = lane & 3;
    int warpM = w >> 1, warpN = w & 1;
    int mBase = blockIdx.y * 128, nBase = blockIdx.x * 128;

    const int8_t* Ag = A + (size_t)mBase * 1024;
    const int8_t* Bg = Bm + (size_t)nBase * 1024;

    int acc[2][8][4];
    #pragma unroll
    for (int mf = 0; mf < 2; mf++)
        #pragma unroll
        for (int nf = 0; nf < 8; nf++)
            #pragma unroll
            for (int i = 0; i < 4; i++) acc[mf][nf][i] = 0;

    auto issue_stage = [&](int s, int buf) {
        int k0 = s * 64;
        #pragma unroll
        for (int j = 0; j < 2; j++) {
            int idx = tid + j * 256;
            int row = idx >> 2, seg = idx & 3;
            uint32_t sa = (uint32_t)__cvta_generic_to_shared(&sm[buf][row * 80 + seg * 16]);
            const int8_t* ga = Ag + (size_t)row * 1024 + k0 + seg * 16;
            asm volatile("cp.async.cg.shared.global [%0], [%1], 16;" :: "r"(sa), "l"(ga));
            uint32_t sb = (uint32_t)__cvta_generic_to_shared(&sm[buf][10240 + row * 80 + seg * 16]);
            const int8_t* gb = Bg + (size_t)row * 1024 + k0 + seg * 16;
            asm volatile("cp.async.cg.shared.global [%0], [%1], 16;" :: "r"(sb), "l"(gb));
        }
        asm volatile("cp.async.commit_group;");
    };

    issue_stage(0, 0);

    for (int s = 0; s < 16; s++) {
        int buf = s & 1;
        if (s < 15) {
            issue_stage(s + 1, buf ^ 1);
            asm volatile("cp.async.wait_group 1;");
        } else {
            asm volatile("cp.async.wait_group 0;");
        }
        __syncthreads();

        const int8_t* As = &sm[buf][0];
        const int8_t* Bs = &sm[buf][10240];
        #pragma unroll
        for (int ks = 0; ks < 2; ks++) {
            int koff = ks * 32;
            uint32_t afr[2][4];
            #pragma unroll
            for (int mf = 0; mf < 2; mf++) {
                int rowb = warpM * 32 + mf * 16 + grp;
                const int8_t* p = As + rowb * 80 + koff + 4 * q;
                afr[mf][0] = *(const uint32_t*)p;
                afr[mf][1] = *(const uint32_t*)(p + 8 * 80);
                afr[mf][2] = *(const uint32_t*)(p + 16);
                afr[mf][3] = *(const uint32_t*)(p + 8 * 80 + 16);
            }
            #pragma unroll
            for (int nf = 0; nf < 8; nf++) {
                int nb = warpN * 64 + nf * 8 + grp;
                const int8_t* p = Bs + nb * 80 + koff + 4 * q;
                uint32_t bfr[2];
                bfr[0] = *(const uint32_t*)p;
                bfr[1] = *(const uint32_t*)(p + 16);
                mma_s8(acc[0][nf], afr[0], bfr);
                mma_s8(acc[1][nf], afr[1], bfr);
            }
        }
        __syncthreads();
    }

    // dequant epilogue: val = s32 * cm * (amax_row/127) * mult (exact in fp32)
    float cmm = g_wcm[midx] * mult;
    #pragma unroll
    for (int mf = 0; mf < 2; mf++) {
        int row = mBase + warpM * 32 + mf * 16 + grp;
        float f0 = cmm * ascale[row];
        float f1 = cmm * ascale[row + 8];
        #pragma unroll
        for (int nf = 0; nf < 8; nf++) {
            int col = nBase + warpN * 64 + nf * 8 + 2 * q;
            float v00 = (float)acc[mf][nf][0] * f0, v01 = (float)acc[mf][nf][1] * f0;
            float v10 = (float)acc[mf][nf][2] * f1, v11 = (float)acc[mf][nf][3] * f1;
            if (OUT_MODE == 0) {
                float* O = (float*)Cout;
                *(float2*)(O + (size_t)row * 1024 + col) = make_float2(v00, v01);
                *(float2*)(O + (size_t)(row + 8) * 1024 + col) = make_float2(v10, v11);
            } else {
                __half* Oh = (__half*)Cout;
                __half* Ol = (__half*)Cout2;
                __half h00 = __float2half_rn(v00), h01 = __float2half_rn(v01);
                __half h10 = __float2half_rn(v10), h11 = __float2half_rn(v11);
                *(half2*)(Oh + (size_t)row * 1024 + col) = __halves2half2(h00, h01);
                *(half2*)(Oh + (size_t)(row + 8) * 1024 + col) = __halves2half2(h10, h11);
                __half l00 = __float2half_rn(v00 - __half2float(h00));
                __half l01 = __float2half_rn(v01 - __half2float(h01));
                __half l10 = __float2half_rn(v10 - __half2float(h10));
                __half l11 = __float2half_rn(v11 - __half2float(h11));
                *(half2*)(Ol + (size_t)row * 1024 + col) = __halves2half2(l00, l01);
                *(half2*)(Ol + (size_t)(row + 8) * 1024 + col) = __halves2half2(l10, l11);
            }
        }
    }
}

// ---------------- flash attention, split-fp16 (hi/lo) for BOTH QK^T and P.V ----------------
__device__ __forceinline__ void mma_f16(float* c, const uint32_t* a, const uint32_t* b)
{
    asm volatile(
        "mma.sync.aligned.m16n8k16.row.col.f32.f16.f16.f32 "
        "{%0,%1,%2,%3}, {%4,%5,%6,%7}, {%8,%9}, {%0,%1,%2,%3};"
        : "+f"(c[0]), "+f"(c[1]), "+f"(c[2]), "+f"(c[3])
        : "r"(a[0]), "r"(a[1]), "r"(a[2]), "r"(a[3]), "r"(b[0]), "r"(b[1]));
}

__device__ __forceinline__ void ldsm4(uint32_t* r, const void* p)
{
    uint32_t a = (uint32_t)__cvta_generic_to_shared(p);
    asm volatile("ldmatrix.sync.aligned.m8n8.x4.shared.b16 {%0,%1,%2,%3}, [%4];"
                 : "=r"(r[0]), "=r"(r[1]), "=r"(r[2]), "=r"(r[3]) : "r"(a));
}

__device__ __forceinline__ void ldsm4t(uint32_t* r, const void* p)
{
    uint32_t a = (uint32_t)__cvta_generic_to_shared(p);
    asm volatile("ldmatrix.sync.aligned.m8n8.x4.trans.shared.b16 {%0,%1,%2,%3}, [%4];"
                 : "=r"(r[0]), "=r"(r[1]), "=r"(r[2]), "=r"(r[3]) : "r"(a));
}

// grid (32 qblocks, 16 heads, 2 batch), 128 threads (4 warps), q tile 64, key chunk 64.
// S = Qh Kh^T + Qh Kl^T + Ql Kh^T ; O += Ph Vh + Ph Vl + Pl Vh  (fp32-accurate both)
__global__ __launch_bounds__(128) void attn_kernel(const __half* __restrict__ Qh,
                                                   const __half* __restrict__ Ql,
                                                   const __half* __restrict__ Kh,
                                                   const __half* __restrict__ Kl,
                                                   const __half* __restrict__ Vh,
                                                   const __half* __restrict__ Vl,
                                                   float* __restrict__ Oout)
{
    const int STR = 72;
    __shared__ __half Qs[64 * STR];     // reused for hi then lo
    __shared__ __half Ksh[64 * STR];
    __shared__ __half Ksl[64 * STR];
    __shared__ __half Vsh[64 * STR];
    __shared__ __half Vsl[64 * STR];

    int b = blockIdx.z, h = blockIdx.y, qb = blockIdx.x;
    int tid = threadIdx.x;
    int w = tid >> 5, lane = tid & 31;
    int grp = lane >> 2, q = lane & 3;

    size_t qoff = (size_t)(b * 2048 + qb * 64) * 1024 + h * 64;
    size_t koff = (size_t)b * 2048 * 1024 + h * 64;

    uint32_t aQh[4][4], aQl[4][4];
    // Q hi
    #pragma unroll
    for (int j = 0; j < 4; j++) {
        int idx = tid + j * 128;
        int row = idx >> 3, seg = idx & 7;
        *(int4*)&Qs[row * STR + seg * 8] = *(const int4*)(Qh + qoff + (size_t)row * 1024 + seg * 8);
    }
    __syncthreads();
    #pragma unroll
    for (int kf = 0; kf < 4; kf++) {
        int r = w * 16 + (lane & 15);
        int c = kf * 16 + ((lane >> 4) << 3);
        ldsm4(aQh[kf], &Qs[r * STR + c]);
    }
    __syncthreads();
    // Q lo (reuse buffer)
    #pragma unroll
    for (int j = 0; j < 4; j++) {
        int idx = tid + j * 128;
        int row = idx >> 3, seg = idx & 7;
        *(int4*)&Qs[row * STR + seg * 8] = *(const int4*)(Ql + qoff + (size_t)row * 1024 + seg * 8);
    }
    __syncthreads();
    #pragma unroll
    for (int kf = 0; kf < 4; kf++) {
        int r = w * 16 + (lane & 15);
        int c = kf * 16 + ((lane >> 4) << 3);
        ldsm4(aQl[kf], &Qs[r * STR + c]);
    }

    float m0 = -1e30f, m1 = -1e30f, l0 = 0.f, l1 = 0.f;
    float o[8][4];
    #pragma unroll
    for (int nf = 0; nf < 8; nf++)
        #pragma unroll
        for (int i = 0; i < 4; i++) o[nf][i] = 0.f;

    for (int j0 = 0; j0 < 2048; j0 += 64) {
        __syncthreads();
        #pragma unroll
        for (int j = 0; j < 4; j++) {
            int idx = tid + j * 128;
            int row = idx >> 3, seg = idx & 7;
            size_t g = koff + (size_t)(j0 + row) * 1024 + seg * 8;
            *(int4*)&Ksh[row * STR + seg * 8] = *(const int4*)(Kh + g);
            *(int4*)&Ksl[row * STR + seg * 8] = *(const int4*)(Kl + g);
            *(int4*)&Vsh[row * STR + seg * 8] = *(const int4*)(Vh + g);
            *(int4*)&Vsl[row * STR + seg * 8] = *(const int4*)(Vl + g);
        }
        __syncthreads();

        // S = Q K^T split precision (16 rows x 64 keys per warp)
        float s[8][4];
        #pragma unroll
        for (int nf = 0; nf < 8; nf++)
            #pragma unroll
            for (int i = 0; i < 4; i++) s[nf][i] = 0.f;

        #pragma unroll
        for (int kf = 0; kf < 4; kf++) {
            #pragma unroll
            for (int np = 0; np < 4; np++) {
                int n = np * 16 + (lane & 7) + ((lane >> 4) & 1) * 8;
                int c = kf * 16 + ((lane >> 3) & 1) * 8;
                uint32_t bKh[4], bKl[4];
                ldsm4(bKh, &Ksh[n * STR + c]);
                ldsm4(bKl, &Ksl[n * STR + c]);
                mma_f16(s[np * 2],     aQh[kf], &bKh[0]);
                mma_f16(s[np * 2 + 1], aQh[kf], &bKh[2]);
                mma_f16(s[np * 2],     aQh[kf], &bKl[0]);
                mma_f16(s[np * 2 + 1], aQh[kf], &bKl[2]);
                mma_f16(s[np * 2],     aQl[kf], &bKh[0]);
                mma_f16(s[np * 2 + 1], aQl[kf], &bKh[2]);
            }
        }

        // online softmax (rows grp, grp+8 of this warp's 16)
        float mx0 = -1e30f, mx1 = -1e30f;
        #pragma unroll
        for (int nf = 0; nf < 8; nf++) {
            mx0 = fmaxf(mx0, fmaxf(s[nf][0], s[nf][1]));
            mx1 = fmaxf(mx1, fmaxf(s[nf][2], s[nf][3]));
        }
        mx0 = fmaxf(mx0, __shfl_xor_sync(0xffffffffu, mx0, 1));
        mx0 = fmaxf(mx0, __shfl_xor_sync(0xffffffffu, mx0, 2));
        mx1 = fmaxf(mx1, __shfl_xor_sync(0xffffffffu, mx1, 1));
        mx1 = fmaxf(mx1, __shfl_xor_sync(0xffffffffu, mx1, 2));
        float mn0 = fmaxf(m0, mx0), mn1 = fmaxf(m1, mx1);
        float corr0 = __expf(m0 - mn0), corr1 = __expf(m1 - mn1);
        m0 = mn0; m1 = mn1;

        float ps0 = 0.f, ps1 = 0.f;
        uint32_t aPh[4][4], aPl[4][4];
        #pragma unroll
        for (int nf = 0; nf < 8; nf++) {
            float p0 = __expf(s[nf][0] - mn0);
            float p1 = __expf(s[nf][1] - mn0);
            float p2 = __expf(s[nf][2] - mn1);
            float p3 = __expf(s[nf][3] - mn1);
            ps0 += p0 + p1; ps1 += p2 + p3;
            __half h0 = __float2half_rn(p0), h1 = __float2half_rn(p1);
            __half h2 = __float2half_rn(p2), h3 = __float2half_rn(p3);
            __half e0 = __float2half_rn(p0 - __half2float(h0));
            __half e1 = __float2half_rn(p1 - __half2float(h1));
            __half e2 = __float2half_rn(p2 - __half2float(h2));
            __half e3 = __float2half_rn(p3 - __half2float(h3));
            int kf = nf >> 1, hi = nf & 1;
            half2 hh01 = __halves2half2(h0, h1), hh23 = __halves2half2(h2, h3);
            half2 ll01 = __halves2half2(e0, e1), ll23 = __halves2half2(e2, e3);
            aPh[kf][hi * 2]     = *(uint32_t*)&hh01;
            aPh[kf][hi * 2 + 1] = *(uint32_t*)&hh23;
            aPl[kf][hi * 2]     = *(uint32_t*)&ll01;
            aPl[kf][hi * 2 + 1] = *(uint32_t*)&ll23;
        }
        ps0 += __shfl_xor_sync(0xffffffffu, ps0, 1);
        ps0 += __shfl_xor_sync(0xffffffffu, ps0, 2);
        ps1 += __shfl_xor_sync(0xffffffffu, ps1, 1);
        ps1 += __shfl_xor_sync(0xffffffffu, ps1, 2);
        l0 = l0 * corr0 + ps0;
        l1 = l1 * corr1 + ps1;
        #pragma unroll
        for (int nf = 0; nf < 8; nf++) {
            o[nf][0] *= corr0; o[nf][1] *= corr0;
            o[nf][2] *= corr1; o[nf][3] *= corr1;
        }

        // O += P V split precision
        #pragma unroll
        for (int kf = 0; kf < 4; kf++) {
            #pragma unroll
            for (int np = 0; np < 4; np++) {
                int kr = kf * 16 + (lane & 7) + ((lane >> 3) & 1) * 8;
                int c = np * 16 + ((lane >> 4) & 1) * 8;
                uint32_t bVh[4], bVl[4];
                ldsm4t(bVh, &Vsh[kr * STR + c]);
                ldsm4t(bVl, &Vsl[kr * STR + c]);
                mma_f16(o[np * 2],     aPh[kf], &bVh[0]);
                mma_f16(o[np * 2 + 1], aPh[kf], &bVh[2]);
                mma_f16(o[np * 2],     aPh[kf], &bVl[0]);
                mma_f16(o[np * 2 + 1], aPh[kf], &bVl[2]);
                mma_f16(o[np * 2],     aPl[kf], &bVh[0]);
                mma_f16(o[np * 2 + 1], aPl[kf], &bVh[2]);
            }
        }
    }

    float inv0 = 1.0f / l0, inv1 = 1.0f / l1;
    int row0 = b * 2048 + qb * 64 + w * 16 + grp;
    #pragma unroll
    for (int nf = 0; nf < 8; nf++) {
        int col = h * 64 + nf * 8 + 2 * q;
        *(float2*)(Oout + (size_t)row0 * 1024 + col) = make_float2(o[nf][0] * inv0, o[nf][1] * inv0);
        *(float2*)(Oout + (size_t)(row0 + 8) * 1024 + col) = make_float2(o[nf][2] * inv1, o[nf][3] * inv1);
    }
}

// ---------------- launch ----------------
extern "C" void kernel_launch(void* const* d_in, const int* in_sizes, int n_in,
                              void* d_out, int out_size)
{
    (void)in_sizes; (void)n_in; (void)out_size;
    const float* x   = (const float*)d_in[0];
    const float* ctx = (const float*)d_in[1];
    const float* wq  = (const float*)d_in[2];
    const float* wk  = (const float*)d_in[3];
    const float* wv  = (const float*)d_in[4];
    const float* wo  = (const float*)d_in[5];
    float* out = (float*)d_out;

    int8_t *xq, *cq, *aq, *wt;
    float *xs, *cs, *as, *attn;
    __half *qh, *ql, *kh, *kl, *vh, *vl;
    cudaGetSymbolAddress((void**)&xq, g_xq);
    cudaGetSymbolAddress((void**)&cq, g_cq);
    cudaGetSymbolAddress((void**)&aq, g_aq);
    cudaGetSymbolAddress((void**)&wt, g_wt);
    cudaGetSymbolAddress((void**)&xs, g_xscale);
    cudaGetSymbolAddress((void**)&cs, g_cscale);
    cudaGetSymbolAddress((void**)&as, g_ascale);
    cudaGetSymbolAddress((void**)&qh, g_qh);
    cudaGetSymbolAddress((void**)&ql, g_ql);
    cudaGetSymbolAddress((void**)&kh, g_kh);
    cudaGetSymbolAddress((void**)&kl, g_kl);
    cudaGetSymbolAddress((void**)&vh, g_vh);
    cudaGetSymbolAddress((void**)&vl, g_vl);
    cudaGetSymbolAddress((void**)&attn, g_attn);

    // weight quantization (ternary int8)
    wsum_kernel<<<dim3(64, 4), 256>>>(wq, wk, wv, wo);
    wscale_kernel<<<4, 64>>>();
    wquant_kernel<<<dim3(1024, 4), 256>>>(wq, wk, wv, wo);

    // activation quantization (int8 + row scale)
    act_quant_i8<<<4096, 256>>>(x, xq, xs);
    act_quant_i8<<<4096, 256>>>(ctx, cq, cs);

    // projections (int8 IMMA); Q pre-scaled by 1/sqrt(64)=0.125; all outputs hi/lo split
    gemm_s8_nt<2><<<dim3(8, 32), 256>>>(xq, wt,           xs, 0, qh, ql, 0.125f);
    gemm_s8_nt<2><<<dim3(8, 32), 256>>>(cq, wt + 1048576, cs, 1, kh, kl, 1.0f);
    gemm_s8_nt<2><<<dim3(8, 32), 256>>>(cq, wt + 2097152, cs, 2, vh, vl, 1.0f);

    // attention (HMMA flash, split-precision scores AND split-precision P.V)
    attn_kernel<<<dim3(32, 16, 2), 128>>>(qh, ql, kh, kl, vh, vl, attn);

    // output projection
    act_quant_i8<<<4096, 256>>>(attn, aq, as);
    gemm_s8_nt<0><<<dim3(8, 32), 256>>>(aq, wt + 3145728, as, 3, out, nullptr, 1.0f);
}

// round 5
// speedup vs baseline: 4.8895x; 1.2897x over previous
#include <cuda_runtime.h>
#include <cuda_fp16.h>
#include <math.h>
#include <stdint.h>

#define EPSF 1e-5f

// ---------------- scratch ----------------
__device__ int8_t g_xq[4194304];     // quantized x int8 [4096,1024]
__device__ int8_t g_cq[4194304];     // quantized context int8
__device__ int8_t g_aq[4194304];     // quantized attn-out int8
__device__ int8_t g_wt[4][1048576];  // ternary weights int8 (q,k,v,o)
__device__ float  g_xscale[4096];
__device__ float  g_cscale[4096];
__device__ float  g_ascale[4096];
__device__ __half g_qh[4194304];     // Q hi fp16 (pre-scaled by 0.125)
__device__ __half g_ql[4194304];     // Q lo fp16 (residual)
__device__ __half g_kh[4194304];     // K hi
__device__ __half g_kl[4194304];     // K lo
__device__ __half g_vh[4194304];     // V hi
__device__ __half g_vl[4194304];     // V lo
__device__ float  g_attn[4194304];   // attention output fp32
__device__ double g_wpart[256];
__device__ float  g_wcm[4];
__device__ float  g_wscale[4];

// ---------------- weight |w| sum (double accumulation, deterministic) ----------------
__global__ __launch_bounds__(256) void wsum_kernel(const float* __restrict__ w0,
                                                   const float* __restrict__ w1,
                                                   const float* __restrict__ w2,
                                                   const float* __restrict__ w3)
{
    const float* w = (blockIdx.y == 0) ? w0 : (blockIdx.y == 1) ? w1 : (blockIdx.y == 2) ? w2 : w3;
    int base = blockIdx.x * 16384;
    int t = threadIdx.x;
    double s = 0.0;
    #pragma unroll
    for (int i = 0; i < 16; i++) {
        float4 v = *(const float4*)(w + base + i * 1024 + t * 4);
        s += (double)fabsf(v.x) + (double)fabsf(v.y) + (double)fabsf(v.z) + (double)fabsf(v.w);
    }
    #pragma unroll
    for (int o = 16; o > 0; o >>= 1) s += __shfl_down_sync(0xffffffffu, s, o);
    __shared__ double ws[8];
    if ((t & 31) == 0) ws[t >> 5] = s;
    __syncthreads();
    if (t == 0) {
        double tot = 0.0;
        #pragma unroll
        for (int i = 0; i < 8; i++) tot += ws[i];
        g_wpart[blockIdx.y * 64 + blockIdx.x] = tot;
    }
}

__global__ void wscale_kernel()
{
    int m = blockIdx.x;
    int t = threadIdx.x; // 64 threads
    double s = g_wpart[m * 64 + t];
    #pragma unroll
    for (int o = 16; o > 0; o >>= 1) s += __shfl_down_sync(0xffffffffu, s, o);
    __shared__ double a[2];
    if ((t & 31) == 0) a[t >> 5] = s;
    __syncthreads();
    if (t == 0) {
        float mean = (float)((a[0] + a[1]) / 1048576.0);
        float cm = fmaxf(mean, EPSF);
        g_wcm[m] = cm;
        g_wscale[m] = 1.0f / cm;
    }
}

__global__ __launch_bounds__(256) void wquant_kernel(const float* __restrict__ w0,
                                                     const float* __restrict__ w1,
                                                     const float* __restrict__ w2,
                                                     const float* __restrict__ w3)
{
    int m = blockIdx.y;
    const float* w = (m == 0) ? w0 : (m == 1) ? w1 : (m == 2) ? w2 : w3;
    float s = g_wscale[m];
    int idx = (blockIdx.x * 256 + threadIdx.x) * 4;
    float4 v = *(const float4*)(w + idx);
    char4 o;
    o.x = (char)fminf(fmaxf(rintf(v.x * s), -1.f), 1.f);
    o.y = (char)fminf(fmaxf(rintf(v.y * s), -1.f), 1.f);
    o.z = (char)fminf(fmaxf(rintf(v.z * s), -1.f), 1.f);
    o.w = (char)fminf(fmaxf(rintf(v.w * s), -1.f), 1.f);
    *(char4*)(g_wt[m] + idx) = o;
}

// ---------------- per-token int8 absmax quant (fused x+ctx via grid.y) ----------------
__global__ __launch_bounds__(256) void act_quant2_i8(const float* __restrict__ in0,
                                                     const float* __restrict__ in1,
                                                     int8_t* __restrict__ out0,
                                                     int8_t* __restrict__ out1,
                                                     float* __restrict__ rs0,
                                                     float* __restrict__ rs1)
{
    const float* in = blockIdx.y ? in1 : in0;
    int8_t* out = blockIdx.y ? out1 : out0;
    float* rowscale = blockIdx.y ? rs1 : rs0;
    int row = blockIdx.x;
    int t = threadIdx.x;
    const float4* ri = (const float4*)(in + (size_t)row * 1024);
    float4 v = ri[t];
    float am = fmaxf(fmaxf(fabsf(v.x), fabsf(v.y)), fmaxf(fabsf(v.z), fabsf(v.w)));
    #pragma unroll
    for (int o = 16; o > 0; o >>= 1) am = fmaxf(am, __shfl_xor_sync(0xffffffffu, am, o));
    __shared__ float wm[8];
    if ((t & 31) == 0) wm[t >> 5] = am;
    __syncthreads();
    am = wm[0];
    #pragma unroll
    for (int i = 1; i < 8; i++) am = fmaxf(am, wm[i]);
    float amax = fmaxf(am, EPSF);
    float scale = 127.0f / amax;
    char4 o4;
    o4.x = (char)fminf(fmaxf(rintf(v.x * scale), -128.f), 127.f);
    o4.y = (char)fminf(fmaxf(rintf(v.y * scale), -128.f), 127.f);
    o4.z = (char)fminf(fmaxf(rintf(v.z * scale), -128.f), 127.f);
    o4.w = (char)fminf(fmaxf(rintf(v.w * scale), -128.f), 127.f);
    *(char4*)(out + (size_t)row * 1024 + t * 4) = o4;
    if (t == 0) rowscale[row] = amax * (1.0f / 127.0f);
}

// ---------------- int8 tensor-core GEMM core (4-stage cp.async pipeline) ----------------
__device__ __forceinline__ void mma_s8(int* c, const uint32_t* a, const uint32_t* b)
{
    asm volatile(
        "mma.sync.aligned.m16n8k32.row.col.s32.s8.s8.s32 "
        "{%0,%1,%2,%3}, {%4,%5,%6,%7}, {%8,%9}, {%0,%1,%2,%3};"
        : "+r"(c[0]), "+r"(c[1]), "+r"(c[2]), "+r"(c[3])
        : "r"(a[0]), "r"(a[1]), "r"(a[2]), "r"(a[3]), "r"(b[0]), "r"(b[1]));
}

// OUT_MODE: 0 = float, 2 = half hi/lo split.  smem: 4 stages x 20480 B.
template <int OUT_MODE>
__device__ __forceinline__ void gemm_body(int8_t* gsm,
                                          const int8_t* __restrict__ A,
                                          const int8_t* __restrict__ Bm,
                                          const float* __restrict__ ascale,
                                          float cmm,
                                          void* __restrict__ Cout,
                                          void* __restrict__ Cout2)
{
    int tid = threadIdx.x;
    int w = tid >> 5, lane = tid & 31;
    int grp = lane >> 2, q = lane & 3;
    int warpM = w >> 1, warpN = w & 1;
    int mBase = blockIdx.y * 128, nBase = blockIdx.x * 128;

    const int8_t* Ag = A + (size_t)mBase * 1024;
    const int8_t* Bg = Bm + (size_t)nBase * 1024;

    int acc[2][8][4];
    #pragma unroll
    for (int mf = 0; mf < 2; mf++)
        #pragma unroll
        for (int nf = 0; nf < 8; nf++)
            #pragma unroll
            for (int i = 0; i < 4; i++) acc[mf][nf][i] = 0;

    auto issue_stage = [&](int s) {
        if (s < 16) {
            int k0 = s * 64;
            int8_t* dst = gsm + (s & 3) * 20480;
            #pragma unroll
            for (int j = 0; j < 2; j++) {
                int idx = tid + j * 256;
                int row = idx >> 2, seg = idx & 3;
                uint32_t sa = (uint32_t)__cvta_generic_to_shared(dst + row * 80 + seg * 16);
                const int8_t* ga = Ag + (size_t)row * 1024 + k0 + seg * 16;
                asm volatile("cp.async.cg.shared.global [%0], [%1], 16;" :: "r"(sa), "l"(ga));
                uint32_t sb = (uint32_t)__cvta_generic_to_shared(dst + 10240 + row * 80 + seg * 16);
                const int8_t* gb = Bg + (size_t)row * 1024 + k0 + seg * 16;
                asm volatile("cp.async.cg.shared.global [%0], [%1], 16;" :: "r"(sb), "l"(gb));
            }
        }
        asm volatile("cp.async.commit_group;");   // always commit (possibly empty)
    };

    issue_stage(0);
    issue_stage(1);
    issue_stage(2);

    for (int s = 0; s < 16; s++) {
        issue_stage(s + 3);
        asm volatile("cp.async.wait_group 3;");
        __syncthreads();

        const int8_t* As = gsm + (s & 3) * 20480;
        const int8_t* Bs = As + 10240;
        #pragma unroll
        for (int ks = 0; ks < 2; ks++) {
            int koff = ks * 32;
            uint32_t afr[2][4];
            #pragma unroll
            for (int mf = 0; mf < 2; mf++) {
                int rowb = warpM * 32 + mf * 16 + grp;
                const int8_t* p = As + rowb * 80 + koff + 4 * q;
                afr[mf][0] = *(const uint32_t*)p;
                afr[mf][1] = *(const uint32_t*)(p + 8 * 80);
                afr[mf][2] = *(const uint32_t*)(p + 16);
                afr[mf][3] = *(const uint32_t*)(p + 8 * 80 + 16);
            }
            #pragma unroll
            for (int nf = 0; nf < 8; nf++) {
                int nb = warpN * 64 + nf * 8 + grp;
                const int8_t* p = Bs + nb * 80 + koff + 4 * q;
                uint32_t bfr[2];
                bfr[0] = *(const uint32_t*)p;
                bfr[1] = *(const uint32_t*)(p + 16);
                mma_s8(acc[0][nf], afr[0], bfr);
                mma_s8(acc[1][nf], afr[1], bfr);
            }
        }
        __syncthreads();
    }

    // dequant epilogue: val = s32 * cm * (amax_row/127) * mult (exact in fp32)
    #pragma unroll
    for (int mf = 0; mf < 2; mf++) {
        int row = mBase + warpM * 32 + mf * 16 + grp;
        float f0 = cmm * ascale[row];
        float f1 = cmm * ascale[row + 8];
        #pragma unroll
        for (int nf = 0; nf < 8; nf++) {
            int col = nBase + warpN * 64 + nf * 8 + 2 * q;
            float v00 = (float)acc[mf][nf][0] * f0, v01 = (float)acc[mf][nf][1] * f0;
            float v10 = (float)acc[mf][nf][2] * f1, v11 = (float)acc[mf][nf][3] * f1;
            if (OUT_MODE == 0) {
                float* O = (float*)Cout;
                *(float2*)(O + (size_t)row * 1024 + col) = make_float2(v00, v01);
                *(float2*)(O + (size_t)(row + 8) * 1024 + col) = make_float2(v10, v11);
            } else {
                __half* Oh = (__half*)Cout;
                __half* Ol = (__half*)Cout2;
                __half h00 = __float2half_rn(v00), h01 = __float2half_rn(v01);
                __half h10 = __float2half_rn(v10), h11 = __float2half_rn(v11);
                *(half2*)(Oh + (size_t)row * 1024 + col) = __halves2half2(h00, h01);
                *(half2*)(Oh + (size_t)(row + 8) * 1024 + col) = __halves2half2(h10, h11);
                __half l00 = __float2half_rn(v00 - __half2float(h00));
                __half l01 = __float2half_rn(v01 - __half2float(h01));
                __half l10 = __float2half_rn(v10 - __half2float(h10));
                __half l11 = __float2half_rn(v11 - __half2float(h11));
                *(half2*)(Ol + (size_t)row * 1024 + col) = __halves2half2(l00, l01);
                *(half2*)(Ol + (size_t)(row + 8) * 1024 + col) = __halves2half2(l10, l11);
            }
        }
    }
}

// fused Q/K/V projection: grid (8, 32, 3)
__global__ __launch_bounds__(256) void gemm_proj(const int8_t* __restrict__ xq,
                                                 const int8_t* __restrict__ cq,
                                                 const float* __restrict__ xs,
                                                 const float* __restrict__ cs,
                                                 const int8_t* __restrict__ wt,
                                                 __half* qh, __half* ql,
                                                 __half* kh, __half* kl,
                                                 __half* vh, __half* vl)
{
    extern __shared__ int8_t gsm[];
    int z = blockIdx.z;
    const int8_t* A = (z == 0) ? xq : cq;
    const float* as_ = (z == 0) ? xs : cs;
    const int8_t* B = wt + (size_t)z * 1048576;
    void* o1 = (z == 0) ? (void*)qh : (z == 1) ? (void*)kh : (void*)vh;
    void* o2 = (z == 0) ? (void*)ql : (z == 1) ? (void*)kl : (void*)vl;
    float cmm = g_wcm[z] * ((z == 0) ? 0.125f : 1.0f);
    gemm_body<2>(gsm, A, B, as_, cmm, o1, o2);
}

// output projection: grid (8, 32)
__global__ __launch_bounds__(256) void gemm_out(const int8_t* __restrict__ aq,
                                                const float* __restrict__ as_,
                                                const int8_t* __restrict__ wt,
                                                float* __restrict__ out)
{
    extern __shared__ int8_t gsm[];
    gemm_body<0>(gsm, aq, wt + 3145728, as_, g_wcm[3], out, nullptr);
}

// ---------------- flash attention, split-fp16 hi/lo, double-buffered K/V ----------------
__device__ __forceinline__ void mma_f16(float* c, const uint32_t* a, const uint32_t* b)
{
    asm volatile(
        "mma.sync.aligned.m16n8k16.row.col.f32.f16.f16.f32 "
        "{%0,%1,%2,%3}, {%4,%5,%6,%7}, {%8,%9}, {%0,%1,%2,%3};"
        : "+f"(c[0]), "+f"(c[1]), "+f"(c[2]), "+f"(c[3])
        : "r"(a[0]), "r"(a[1]), "r"(a[2]), "r"(a[3]), "r"(b[0]), "r"(b[1]));
}

__device__ __forceinline__ void ldsm4(uint32_t* r, const void* p)
{
    uint32_t a = (uint32_t)__cvta_generic_to_shared(p);
    asm volatile("ldmatrix.sync.aligned.m8n8.x4.shared.b16 {%0,%1,%2,%3}, [%4];"
                 : "=r"(r[0]), "=r"(r[1]), "=r"(r[2]), "=r"(r[3]) : "r"(a));
}

__device__ __forceinline__ void ldsm4t(uint32_t* r, const void* p)
{
    uint32_t a = (uint32_t)__cvta_generic_to_shared(p);
    asm volatile("ldmatrix.sync.aligned.m8n8.x4.trans.shared.b16 {%0,%1,%2,%3}, [%4];"
                 : "=r"(r[0]), "=r"(r[1]), "=r"(r[2]), "=r"(r[3]) : "r"(a));
}

// grid (32 qblocks, 16 heads, 2 batch), 128 threads (4 warps).
// dynamic smem: 2 stages x 4 buffers (Ksh,Ksl,Vsh,Vsl) x 64x72 halfs = 73728 B.
// Q is staged through stage-0 space before the pipeline starts.
__global__ __launch_bounds__(128, 3) void attn_kernel(const __half* __restrict__ Qh,
                                                      const __half* __restrict__ Ql,
                                                      const __half* __restrict__ Kh,
                                                      const __half* __restrict__ Kl,
                                                      const __half* __restrict__ Vh,
                                                      const __half* __restrict__ Vl,
                                                      float* __restrict__ Oout)
{
    const int STR = 72;
    const int BUF = 64 * STR;            // 4608 halfs = 9216 bytes
    extern __shared__ __half smema[];    // [2][4][BUF]

    int b = blockIdx.z, h = blockIdx.y, qb = blockIdx.x;
    int tid = threadIdx.x;
    int w = tid >> 5, lane = tid & 31;
    int grp = lane >> 2, q = lane & 3;

    size_t qoff = (size_t)(b * 2048 + qb * 64) * 1024 + h * 64;
    size_t koff = (size_t)b * 2048 * 1024 + h * 64;

    // ---- stage Q hi/lo through smem (before cp.async pipeline touches it) ----
    uint32_t aQh[4][4], aQl[4][4];
    {
        __half* Qs = smema;
        #pragma unroll
        for (int j = 0; j < 4; j++) {
            int idx = tid + j * 128;
            int row = idx >> 3, seg = idx & 7;
            *(int4*)&Qs[row * STR + seg * 8] = *(const int4*)(Qh + qoff + (size_t)row * 1024 + seg * 8);
        }
        __syncthreads();
        #pragma unroll
        for (int kf = 0; kf < 4; kf++) {
            int r = w * 16 + (lane & 15);
            int c = kf * 16 + ((lane >> 4) << 3);
            ldsm4(aQh[kf], &Qs[r * STR + c]);
        }
        __syncthreads();
        #pragma unroll
        for (int j = 0; j < 4; j++) {
            int idx = tid + j * 128;
            int row = idx >> 3, seg = idx & 7;
            *(int4*)&Qs[row * STR + seg * 8] = *(const int4*)(Ql + qoff + (size_t)row * 1024 + seg * 8);
        }
        __syncthreads();
        #pragma unroll
        for (int kf = 0; kf < 4; kf++) {
            int r = w * 16 + (lane & 15);
            int c = kf * 16 + ((lane >> 4) << 3);
            ldsm4(aQl[kf], &Qs[r * STR + c]);
        }
        __syncthreads();   // Q frags in regs; smem free for the pipeline
    }

    // K/V prefetch: stage st holds Ksh|Ksl|Vsh|Vsl each BUF halfs
    auto issue_kv = [&](int s, int st) {
        int j0 = s * 64;
        __half* base = smema + st * 4 * BUF;
        #pragma unroll
        for (int j = 0; j < 4; j++) {
            int idx = tid + j * 128;
            int row = idx >> 3, seg = idx & 7;
            size_t g = koff + (size_t)(j0 + row) * 1024 + seg * 8;
            uint32_t d = (uint32_t)__cvta_generic_to_shared(base + row * STR + seg * 8);
            asm volatile("cp.async.cg.shared.global [%0], [%1], 16;" :: "r"(d), "l"(Kh + g));
            asm volatile("cp.async.cg.shared.global [%0], [%1], 16;" :: "r"(d + 9216u), "l"(Kl + g));
            asm volatile("cp.async.cg.shared.global [%0], [%1], 16;" :: "r"(d + 18432u), "l"(Vh + g));
            asm volatile("cp.async.cg.shared.global [%0], [%1], 16;" :: "r"(d + 27648u), "l"(Vl + g));
        }
        asm volatile("cp.async.commit_group;");
    };

    issue_kv(0, 0);

    float m0 = -1e30f, m1 = -1e30f, l0 = 0.f, l1 = 0.f;
    float o[8][4];
    #pragma unroll
    for (int nf = 0; nf < 8; nf++)
        #pragma unroll
        for (int i = 0; i < 4; i++) o[nf][i] = 0.f;

    for (int t = 0; t < 32; t++) {
        int buf = t & 1;
        if (t < 31) {
            issue_kv(t + 1, buf ^ 1);
            asm volatile("cp.async.wait_group 1;");
        } else {
            asm volatile("cp.async.wait_group 0;");
        }
        __syncthreads();

        const __half* Ksh = smema + buf * 4 * BUF;
        const __half* Ksl = Ksh + BUF;
        const __half* Vsh = Ksh + 2 * BUF;
        const __half* Vsl = Ksh + 3 * BUF;

        // S = Q K^T split precision (16 rows x 64 keys per warp)
        float s[8][4];
        #pragma unroll
        for (int nf = 0; nf < 8; nf++)
            #pragma unroll
            for (int i = 0; i < 4; i++) s[nf][i] = 0.f;

        #pragma unroll
        for (int kf = 0; kf < 4; kf++) {
            #pragma unroll
            for (int np = 0; np < 4; np++) {
                int n = np * 16 + (lane & 7) + ((lane >> 4) & 1) * 8;
                int c = kf * 16 + ((lane >> 3) & 1) * 8;
                uint32_t bKh[4], bKl[4];
                ldsm4(bKh, &Ksh[n * STR + c]);
                ldsm4(bKl, &Ksl[n * STR + c]);
                mma_f16(s[np * 2],     aQh[kf], &bKh[0]);
                mma_f16(s[np * 2 + 1], aQh[kf], &bKh[2]);
                mma_f16(s[np * 2],     aQh[kf], &bKl[0]);
                mma_f16(s[np * 2 + 1], aQh[kf], &bKl[2]);
                mma_f16(s[np * 2],     aQl[kf], &bKh[0]);
                mma_f16(s[np * 2 + 1], aQl[kf], &bKh[2]);
            }
        }

        // online softmax (rows grp, grp+8 of this warp's 16)
        float mx0 = -1e30f, mx1 = -1e30f;
        #pragma unroll
        for (int nf = 0; nf < 8; nf++) {
            mx0 = fmaxf(mx0, fmaxf(s[nf][0], s[nf][1]));
            mx1 = fmaxf(mx1, fmaxf(s[nf][2], s[nf][3]));
        }
        mx0 = fmaxf(mx0, __shfl_xor_sync(0xffffffffu, mx0, 1));
        mx0 = fmaxf(mx0, __shfl_xor_sync(0xffffffffu, mx0, 2));
        mx1 = fmaxf(mx1, __shfl_xor_sync(0xffffffffu, mx1, 1));
        mx1 = fmaxf(mx1, __shfl_xor_sync(0xffffffffu, mx1, 2));
        float mn0 = fmaxf(m0, mx0), mn1 = fmaxf(m1, mx1);
        float corr0 = __expf(m0 - mn0), corr1 = __expf(m1 - mn1);
        m0 = mn0; m1 = mn1;

        float ps0 = 0.f, ps1 = 0.f;
        uint32_t aPh[4][4], aPl[4][4];
        #pragma unroll
        for (int nf = 0; nf < 8; nf++) {
            float p0 = __expf(s[nf][0] - mn0);
            float p1 = __expf(s[nf][1] - mn0);
            float p2 = __expf(s[nf][2] - mn1);
            float p3 = __expf(s[nf][3] - mn1);
            ps0 += p0 + p1; ps1 += p2 + p3;
            __half h0 = __float2half_rn(p0), h1 = __float2half_rn(p1);
            __half h2 = __float2half_rn(p2), h3 = __float2half_rn(p3);
            __half e0 = __float2half_rn(p0 - __half2float(h0));
            __half e1 = __float2half_rn(p1 - __half2float(h1));
            __half e2 = __float2half_rn(p2 - __half2float(h2));
            __half e3 = __float2half_rn(p3 - __half2float(h3));
            int kf = nf >> 1, hi = nf & 1;
            half2 hh01 = __halves2half2(h0, h1), hh23 = __halves2half2(h2, h3);
            half2 ll01 = __halves2half2(e0, e1), ll23 = __halves2half2(e2, e3);
            aPh[kf][hi * 2]     = *(uint32_t*)&hh01;
            aPh[kf][hi * 2 + 1] = *(uint32_t*)&hh23;
            aPl[kf][hi * 2]     = *(uint32_t*)&ll01;
            aPl[kf][hi * 2 + 1] = *(uint32_t*)&ll23;
        }
        ps0 += __shfl_xor_sync(0xffffffffu, ps0, 1);
        ps0 += __shfl_xor_sync(0xffffffffu, ps0, 2);
        ps1 += __shfl_xor_sync(0xffffffffu, ps1, 1);
        ps1 += __shfl_xor_sync(0xffffffffu, ps1, 2);
        l0 = l0 * corr0 + ps0;
        l1 = l1 * corr1 + ps1;
        #pragma unroll
        for (int nf = 0; nf < 8; nf++) {
            o[nf][0] *= corr0; o[nf][1] *= corr0;
            o[nf][2] *= corr1; o[nf][3] *= corr1;
        }

        // O += P V split precision
        #pragma unroll
        for (int kf = 0; kf < 4; kf++) {
            #pragma unroll
            for (int np = 0; np < 4; np++) {
                int kr = kf * 16 + (lane & 7) + ((lane >> 3) & 1) * 8;
                int c = np * 16 + ((lane >> 4) & 1) * 8;
                uint32_t bVh[4], bVl[4];
                ldsm4t(bVh, &Vsh[kr * STR + c]);
                ldsm4t(bVl, &Vsl[kr * STR + c]);
                mma_f16(o[np * 2],     aPh[kf], &bVh[0]);
                mma_f16(o[np * 2 + 1], aPh[kf], &bVh[2]);
                mma_f16(o[np * 2],     aPh[kf], &bVl[0]);
                mma_f16(o[np * 2 + 1], aPh[kf], &bVl[2]);
                mma_f16(o[np * 2],     aPl[kf], &bVh[0]);
                mma_f16(o[np * 2 + 1], aPl[kf], &bVh[2]);
            }
        }
        __syncthreads();   // readers done before this buffer is refilled next iter
    }

    float inv0 = 1.0f / l0, inv1 = 1.0f / l1;
    int row0 = b * 2048 + qb * 64 + w * 16 + grp;
    #pragma unroll
    for (int nf = 0; nf < 8; nf++) {
        int col = h * 64 + nf * 8 + 2 * q;
        *(float2*)(Oout + (size_t)row0 * 1024 + col) = make_float2(o[nf][0] * inv0, o[nf][1] * inv0);
        *(float2*)(Oout + (size_t)(row0 + 8) * 1024 + col) = make_float2(o[nf][2] * inv1, o[nf][3] * inv1);
    }
}

// ---------------- single-input act quant (attention output) ----------------
__global__ __launch_bounds__(256) void act_quant_i8(const float* __restrict__ in,
                                                    int8_t* __restrict__ out,
                                                    float* __restrict__ rowscale)
{
    int row = blockIdx.x;
    int t = threadIdx.x;
    const float4* ri = (const float4*)(in + (size_t)row * 1024);
    float4 v = ri[t];
    float am = fmaxf(fmaxf(fabsf(v.x), fabsf(v.y)), fmaxf(fabsf(v.z), fabsf(v.w)));
    #pragma unroll
    for (int o = 16; o > 0; o >>= 1) am = fmaxf(am, __shfl_xor_sync(0xffffffffu, am, o));
    __shared__ float wm[8];
    if ((t & 31) == 0) wm[t >> 5] = am;
    __syncthreads();
    am = wm[0];
    #pragma unroll
    for (int i = 1; i < 8; i++) am = fmaxf(am, wm[i]);
    float amax = fmaxf(am, EPSF);
    float scale = 127.0f / amax;
    char4 o4;
    o4.x = (char)fminf(fmaxf(rintf(v.x * scale), -128.f), 127.f);
    o4.y = (char)fminf(fmaxf(rintf(v.y * scale), -128.f), 127.f);
    o4.z = (char)fminf(fmaxf(rintf(v.z * scale), -128.f), 127.f);
    o4.w = (char)fminf(fmaxf(rintf(v.w * scale), -128.f), 127.f);
    *(char4*)(out + (size_t)row * 1024 + t * 4) = o4;
    if (t == 0) rowscale[row] = amax * (1.0f / 127.0f);
}

// ---------------- launch ----------------
extern "C" void kernel_launch(void* const* d_in, const int* in_sizes, int n_in,
                              void* d_out, int out_size)
{
    (void)in_sizes; (void)n_in; (void)out_size;
    const float* x   = (const float*)d_in[0];
    const float* ctx = (const float*)d_in[1];
    const float* wq  = (const float*)d_in[2];
    const float* wk  = (const float*)d_in[3];
    const float* wv  = (const float*)d_in[4];
    const float* wo  = (const float*)d_in[5];
    float* out = (float*)d_out;

    int8_t *xq, *cq, *aq, *wt;
    float *xs, *cs, *as, *attn;
    __half *qh, *ql, *kh, *kl, *vh, *vl;
    cudaGetSymbolAddress((void**)&xq, g_xq);
    cudaGetSymbolAddress((void**)&cq, g_cq);
    cudaGetSymbolAddress((void**)&aq, g_aq);
    cudaGetSymbolAddress((void**)&wt, g_wt);
    cudaGetSymbolAddress((void**)&xs, g_xscale);
    cudaGetSymbolAddress((void**)&cs, g_cscale);
    cudaGetSymbolAddress((void**)&as, g_ascale);
    cudaGetSymbolAddress((void**)&qh, g_qh);
    cudaGetSymbolAddress((void**)&ql, g_ql);
    cudaGetSymbolAddress((void**)&kh, g_kh);
    cudaGetSymbolAddress((void**)&kl, g_kl);
    cudaGetSymbolAddress((void**)&vh, g_vh);
    cudaGetSymbolAddress((void**)&vl, g_vl);
    cudaGetSymbolAddress((void**)&attn, g_attn);

    // opt-in dynamic smem (host-side attribute set; idempotent, capture-safe)
    cudaFuncSetAttribute(gemm_proj, cudaFuncAttributeMaxDynamicSharedMemorySize, 81920);
    cudaFuncSetAttribute(gemm_out,  cudaFuncAttributeMaxDynamicSharedMemorySize, 81920);
    cudaFuncSetAttribute(attn_kernel, cudaFuncAttributeMaxDynamicSharedMemorySize, 73728);

    // weight quantization (ternary int8)
    wsum_kernel<<<dim3(64, 4), 256>>>(wq, wk, wv, wo);
    wscale_kernel<<<4, 64>>>();
    wquant_kernel<<<dim3(1024, 4), 256>>>(wq, wk, wv, wo);

    // activation quantization (x and ctx fused)
    act_quant2_i8<<<dim3(4096, 2), 256>>>(x, ctx, xq, cq, xs, cs);

    // fused Q/K/V projections (int8 IMMA, 4-stage pipeline); Q pre-scaled by 0.125
    gemm_proj<<<dim3(8, 32, 3), 256, 81920>>>(xq, cq, xs, cs, wt, qh, ql, kh, kl, vh, vl);

    // attention (HMMA flash, split-precision QK^T and P.V, double-buffered K/V)
    attn_kernel<<<dim3(32, 16, 2), 128, 73728>>>(qh, ql, kh, kl, vh, vl, attn);

    // output projection
    act_quant_i8<<<4096, 256>>>(attn, aq, as);
    gemm_out<<<dim3(8, 32), 256, 81920>>>(aq, as, wt, out);
}